// round 12
// baseline (speedup 1.0000x reference)
#include <cuda_runtime.h>
#include <math.h>

// TopKRouter: logits = x @ W^T (N=32768, D=2048, E=64), top-2, softmax, one-hot mask.
// Outputs (all f32, concatenated): mask[N*64] | weights[N*2] | indices_as_float[N*2]
//
// Packed fp32x2 FMA (fma.rn.f32x2, Blackwell FFMA2) inner loop: 2x fp32 throughput,
// bit-identical fp32 arithmetic (exact top-2 ordering). Ping-pong smem staging,
// ONE __syncthreads per K-chunk, conflict-free STS/LDS. x via __ldcs / outputs via
// __stcs so the 256 MB x stream never evicts the 512 KB W from L2.
// TILE = 32 tokens (grid 1024): per-SM load 7 vs avg 6.92 -> ~1% quantization loss
// (tile=128 loses 13.5%: 108 SMs carry 2 CTAs, 40 carry 1, makespan 2.0 vs 1.73).

#define DIMK 2048
#define NEXP 64
#define TOK_TILE 32
#define KC 16
#define NTHREADS 128
#define XS_S 34                       // xs row stride (floats), even for 8B-aligned LDS.64
#define STAGE_FLOATS (KC * XS_S + KC * 68)   // 544 + 1088 = 1632

#define FMA_F32X2(d, a, b, c) \
    asm("fma.rn.f32x2 %0, %1, %2, %3;" : "=l"(d) : "l"(a), "l"(b), "l"(c))

#define SPLAT_F32X2(out, f) \
    asm("mov.b64 %0, {%1, %1};" : "=l"(out) : "r"(__float_as_uint(f)))

#define UNPACK_F32X2_(lo, hi, in) \
    asm("mov.b64 {%0, %1}, %2;" : "=r"(lo), "=r"(hi) : "l"(in))

__global__ __launch_bounds__(NTHREADS, 6) void router_kernel(
    const float* __restrict__ x,
    const float* __restrict__ gw,
    float* __restrict__ mask_out,
    float* __restrict__ wts_out,
    float* __restrict__ idx_out,
    int n_tokens)
{
    // Shared memory union:
    //   staging (ping-pong): 2 x 1632 floats = 3264
    //   epilogue: lg[32][65] = 2080 floats (fits inside staging)
    __shared__ float sbuf[2 * STAGE_FLOATS];
    __shared__ int s_i1[TOK_TILE];
    __shared__ int s_i2[TOK_TILE];

    float (*lg)[65] = (float (*)[65])sbuf;

    const int tid = threadIdx.x;
    const int tx = tid & 15;   // token-pair group 0..15 (2 tokens each)
    const int ty = tid >> 4;   // expert-group 0..7 (8 experts each)

    const long tokb = (long)blockIdx.x * TOK_TILE;

    // ---- global-load thread mappings (conflict-free STS) ----
    // x tile: 32 rows x 16 k. Warp w owns k-columns 4w..4w+3; lane owns the row.
    // One float4 per thread per chunk (32*16 = 512 floats = 128 thr * 4).
    //   STS bank = ((4w+i)*34 + lane) % 32 = const + lane -> conflict-free.
    const int xl_k = (tid >> 5) * 4;  // k offset 0,4,8,12 (per warp)
    const int xl_r = tid & 31;        // row 0..31
    // w tile: 64 experts x 16 k. Threads 0-63: k 0-7; threads 64-127: k 8-15.
    //   STS bank = (4*(8h+i) + e) % 32 = 4i + e(lane) -> conflict-free.
    const int wl_e = tid & 63;        // expert 0..63
    const int wl_k = (tid >> 6) * 8;  // 0 or 8

    const float* xptr = x + (tokb + xl_r) * DIMK + xl_k;
    const float* wptr = gw + (long)wl_e * DIMK + wl_k;

    // accumulators: 2 tokens x 4 expert-pairs (8 experts), packed f32x2
    unsigned long long acc2[2][4];
#pragma unroll
    for (int i = 0; i < 2; i++)
#pragma unroll
        for (int j = 0; j < 4; j++) acc2[i][j] = 0ULL;

    float4 px, pw0, pw1;

    // ---- stage accessors, s in {0,1} ----
    auto xs_at = [&](int s, int k, int row) -> float& {
        return sbuf[s * STAGE_FLOATS + k * XS_S + row];
    };
    auto ws_at = [&](int s, int k, int e) -> float& {
        return sbuf[s * STAGE_FLOATS + KC * XS_S + k * 68 + e];
    };

    // prefetch chunk 0 and store into stage 0
    px  = __ldcs((const float4*)xptr);
    pw0 = *(const float4*)(wptr);
    pw1 = *(const float4*)(wptr + 4);

    xs_at(0, xl_k + 0, xl_r) = px.x;
    xs_at(0, xl_k + 1, xl_r) = px.y;
    xs_at(0, xl_k + 2, xl_r) = px.z;
    xs_at(0, xl_k + 3, xl_r) = px.w;
    ws_at(0, wl_k + 0, wl_e) = pw0.x;
    ws_at(0, wl_k + 1, wl_e) = pw0.y;
    ws_at(0, wl_k + 2, wl_e) = pw0.z;
    ws_at(0, wl_k + 3, wl_e) = pw0.w;
    ws_at(0, wl_k + 4, wl_e) = pw1.x;
    ws_at(0, wl_k + 5, wl_e) = pw1.y;
    ws_at(0, wl_k + 6, wl_e) = pw1.z;
    ws_at(0, wl_k + 7, wl_e) = pw1.w;
    __syncthreads();

    const int NCHUNK = DIMK / KC;  // 128
    for (int c = 0; c < NCHUNK; ++c) {
        const int cur = c & 1;
        const int nxt = cur ^ 1;

        // prefetch next chunk (global loads overlap compute below)
        if (c + 1 < NCHUNK) {
            px  = __ldcs((const float4*)(xptr + (c + 1) * KC));
            pw0 = *(const float4*)(wptr + (c + 1) * KC);
            pw1 = *(const float4*)(wptr + (c + 1) * KC + 4);
        }

        // compute on stage `cur`: 2 tokens x 4 expert-pairs over Kc=16
        const float* xs_c = &sbuf[cur * STAGE_FLOATS];
        const float* ws_c = &sbuf[cur * STAGE_FLOATS + KC * XS_S];
#pragma unroll
        for (int kk = 0; kk < KC; kk++) {
            // a: 2 tokens (LDS.64, 8B-aligned; same-addr lanes broadcast)
            float2 a01 = *(const float2*)(xs_c + kk * XS_S + tx * 2);
            // b: 8 consecutive experts = 4 pre-packed f32x2 (16B-aligned)
            const ulonglong2* bp = (const ulonglong2*)(ws_c + kk * 68 + ty * 8);
            ulonglong2 bq0 = bp[0];
            ulonglong2 bq1 = bp[1];
            unsigned long long b2[4] = {bq0.x, bq0.y, bq1.x, bq1.y};

            unsigned long long as2[2];
            SPLAT_F32X2(as2[0], a01.x);
            SPLAT_F32X2(as2[1], a01.y);

#pragma unroll
            for (int i = 0; i < 2; i++)
#pragma unroll
                for (int j = 0; j < 4; j++)
                    FMA_F32X2(acc2[i][j], as2[i], b2[j], acc2[i][j]);
        }

        // store prefetched chunk into stage `nxt` (disjoint from `cur`)
        if (c + 1 < NCHUNK) {
            xs_at(nxt, xl_k + 0, xl_r) = px.x;
            xs_at(nxt, xl_k + 1, xl_r) = px.y;
            xs_at(nxt, xl_k + 2, xl_r) = px.z;
            xs_at(nxt, xl_k + 3, xl_r) = px.w;
            ws_at(nxt, wl_k + 0, wl_e) = pw0.x;
            ws_at(nxt, wl_k + 1, wl_e) = pw0.y;
            ws_at(nxt, wl_k + 2, wl_e) = pw0.z;
            ws_at(nxt, wl_k + 3, wl_e) = pw0.w;
            ws_at(nxt, wl_k + 4, wl_e) = pw1.x;
            ws_at(nxt, wl_k + 5, wl_e) = pw1.y;
            ws_at(nxt, wl_k + 6, wl_e) = pw1.z;
            ws_at(nxt, wl_k + 7, wl_e) = pw1.w;
        }

        // one barrier per chunk: orders (a) this chunk's compute-reads before
        // next iteration's overwrite of `cur`, and (b) stores to `nxt` before
        // next iteration's compute-reads of it.
        __syncthreads();
    }

    // ---- epilogue: logits -> smem (staging buffers dead; reuse as lg) ----
#pragma unroll
    for (int i = 0; i < 2; i++)
#pragma unroll
        for (int j = 0; j < 4; j++) {
            unsigned int lo, hi;
            UNPACK_F32X2_(lo, hi, acc2[i][j]);
            lg[tx * 2 + i][ty * 8 + 2 * j + 0] = __uint_as_float(lo);
            lg[tx * 2 + i][ty * 8 + 2 * j + 1] = __uint_as_float(hi);
        }
    __syncthreads();

    // per-token branchless top-2 scan: threads 0..31 each own one token.
    // Row read: bank = (65*t + e) % 32 = (t + e) % 32 -> conflict-free.
    if (tid < TOK_TILE) {
        float m1 = -INFINITY, m2 = -INFINITY;
        int i1 = 0, i2 = 0;
#pragma unroll
        for (int e = 0; e < NEXP; e++) {
            float v = lg[tid][e];
            bool gt1 = v > m1;
            bool gt2 = v > m2;
            m2 = gt1 ? m1 : (gt2 ? v : m2);
            i2 = gt1 ? i1 : (gt2 ? e : i2);
            m1 = gt1 ? v : m1;
            i1 = gt1 ? e : i1;
        }
        // softmax over [m1, m2] (m1 >= m2, numerically stable)
        float t  = expf(m2 - m1);
        float w1 = 1.0f / (1.0f + t);
        float w2 = t * w1;

        const long tok = tokb + tid;
        __stcs(&wts_out[tok * 2 + 0], w1);
        __stcs(&wts_out[tok * 2 + 1], w2);
        __stcs(&idx_out[tok * 2 + 0], (float)i1);
        __stcs(&idx_out[tok * 2 + 1], (float)i2);
        s_i1[tid] = i1;
        s_i2[tid] = i2;
    }
    __syncthreads();

    // cooperative coalesced mask write: 32 tokens x 64 experts (streaming)
    float* mrow = mask_out + tokb * NEXP;
#pragma unroll
    for (int j = 0; j < (TOK_TILE * NEXP) / NTHREADS; j++) {  // 16
        int flat = j * NTHREADS + tid;
        int t_ = flat >> 6;
        int e  = flat & 63;
        __stcs(&mrow[flat], (e == s_i1[t_] || e == s_i2[t_]) ? 1.0f : 0.0f);
    }
    (void)n_tokens;
}

extern "C" void kernel_launch(void* const* d_in, const int* in_sizes, int n_in,
                              void* d_out, int out_size) {
    const float* x  = (const float*)d_in[0];
    const float* gw = (const float*)d_in[1];

    const int n_tokens = in_sizes[0] / DIMK;  // 32768

    float* mask = (float*)d_out;
    float* wts  = mask + (long)n_tokens * NEXP;
    float* idxf = wts + (long)n_tokens * 2;

    const int nblocks = n_tokens / TOK_TILE;  // 1024
    router_kernel<<<nblocks, NTHREADS>>>(x, gw, mask, wts, idxf, n_tokens);

    (void)n_in; (void)out_size;
}

// round 14
// speedup vs baseline: 1.3844x; 1.3844x over previous
#include <cuda_runtime.h>
#include <math.h>

// TopKRouter: logits = x @ W^T (N=32768, D=2048, E=64), top-2, softmax, one-hot mask.
// Outputs (all f32, concatenated): mask[N*64] | weights[N*2] | indices_as_float[N*2]
//
// R12 post-mortem: tile-32 (2x8 per-thread) was smem-crossbar-bound (L1=87.7%,
// fma=29.6%, 390us). Restore 8x8 per-thread tile: loads/FMA 0.625 -> 0.25, so the
// fma pipe (FFMA2, rt=2, ~115us floor) becomes the binding resource.
// Crossbar audit per warp per k: a 2xLDS.128 (16 addrs -> 2 wf each) + b 2xLDS.128
// (broadcast -> 1 wf each) + ~1.5 wf staging = ~7.5 wf vs 16 fma cyc -> ~47% L1.
// TOK_TILE=128, grid 256, occ 2. Ping-pong staging, ONE barrier per K-chunk,
// conflict-free STS/LDS, __ldcs on x / __stcs on outputs to keep W L2-resident.

#define DIMK 2048
#define NEXP 64
#define TOK_TILE 128
#define KC 16
#define NTHREADS 128
#define STAGE_FLOATS 3200   // xs 16*132 + ws 16*68

#define FMA_F32X2(d, a, b, c) \
    asm("fma.rn.f32x2 %0, %1, %2, %3;" : "=l"(d) : "l"(a), "l"(b), "l"(c))

#define SPLAT_F32X2(out, f) \
    asm("mov.b64 %0, {%1, %1};" : "=l"(out) : "r"(__float_as_uint(f)))

#define UNPACK_F32X2_(lo, hi, in) \
    asm("mov.b64 {%0, %1}, %2;" : "=r"(lo), "=r"(hi) : "l"(in))

__global__ __launch_bounds__(NTHREADS, 2) void router_kernel(
    const float* __restrict__ x,
    const float* __restrict__ gw,
    float* __restrict__ mask_out,
    float* __restrict__ wts_out,
    float* __restrict__ idx_out,
    int n_tokens)
{
    // Shared memory union:
    //   staging (ping-pong): 2 x 3200 floats = 6400
    //   epilogue: lg[128][65] = 8320 floats  (larger -> sizes the buffer)
    __shared__ float sbuf[TOK_TILE * 65];
    __shared__ int s_i1[TOK_TILE];
    __shared__ int s_i2[TOK_TILE];

    float (*lg)[65] = (float (*)[65])sbuf;

    const int tid = threadIdx.x;
    const int tx = tid & 15;   // token-group 0..15 (8 tokens each)
    const int ty = tid >> 4;   // expert-group 0..7 (8 experts each)

    const long tokb = (long)blockIdx.x * TOK_TILE;

    // ---- global-load thread mappings (conflict-free STS) ----
    // x tile: 128 rows x 16 k. Warp w owns k-columns 4w..4w+3; lane owns a row.
    //   STS bank = ((4w+i)*132 + lane) % 32 = const + lane -> conflict-free.
    const int xl_k = (tid >> 5) * 4;  // k offset 0,4,8,12 (per warp)
    const int xl_r = tid & 31;        // row 0..31 (plus +32/+64/+96)
    // w tile: 64 experts x 16 k. Threads 0-63: k 0-7; threads 64-127: k 8-15.
    //   STS bank = (4*(8h+i) + e) % 32 = 4i + e(lane) -> conflict-free.
    const int wl_e = tid & 63;        // expert 0..63
    const int wl_k = (tid >> 6) * 8;  // 0 or 8

    const float* xptr = x + (tokb + xl_r) * DIMK + xl_k;
    const float* wptr = gw + (long)wl_e * DIMK + wl_k;

    // accumulators: 8 tokens x 4 expert-pairs (8 experts), packed f32x2
    unsigned long long acc2[8][4];
#pragma unroll
    for (int i = 0; i < 8; i++)
#pragma unroll
        for (int j = 0; j < 4; j++) acc2[i][j] = 0ULL;

    float4 px[4], pw[2];

    // ---- stage accessors, s in {0,1} ----
    auto xs_at = [&](int s, int k, int row) -> float& {
        return sbuf[s * STAGE_FLOATS + k * 132 + row];
    };
    auto ws_at = [&](int s, int k, int e) -> float& {
        return sbuf[s * STAGE_FLOATS + KC * 132 + k * 68 + e];
    };

    // prefetch chunk 0 and store into stage 0
#pragma unroll
    for (int r = 0; r < 4; r++)
        px[r] = __ldcs((const float4*)(xptr + (long)r * 32 * DIMK));
    pw[0] = *(const float4*)(wptr);
    pw[1] = *(const float4*)(wptr + 4);

#pragma unroll
    for (int r = 0; r < 4; r++) {
        const int row = xl_r + r * 32;
        xs_at(0, xl_k + 0, row) = px[r].x;
        xs_at(0, xl_k + 1, row) = px[r].y;
        xs_at(0, xl_k + 2, row) = px[r].z;
        xs_at(0, xl_k + 3, row) = px[r].w;
    }
    ws_at(0, wl_k + 0, wl_e) = pw[0].x;
    ws_at(0, wl_k + 1, wl_e) = pw[0].y;
    ws_at(0, wl_k + 2, wl_e) = pw[0].z;
    ws_at(0, wl_k + 3, wl_e) = pw[0].w;
    ws_at(0, wl_k + 4, wl_e) = pw[1].x;
    ws_at(0, wl_k + 5, wl_e) = pw[1].y;
    ws_at(0, wl_k + 6, wl_e) = pw[1].z;
    ws_at(0, wl_k + 7, wl_e) = pw[1].w;
    __syncthreads();

    const int NCHUNK = DIMK / KC;  // 128
    for (int c = 0; c < NCHUNK; ++c) {
        const int cur = c & 1;
        const int nxt = cur ^ 1;

        // prefetch next chunk (global loads overlap compute below)
        if (c + 1 < NCHUNK) {
            const float* xn = xptr + (c + 1) * KC;
            const float* wn = wptr + (c + 1) * KC;
#pragma unroll
            for (int r = 0; r < 4; r++)
                px[r] = __ldcs((const float4*)(xn + (long)r * 32 * DIMK));
            pw[0] = *(const float4*)(wn);
            pw[1] = *(const float4*)(wn + 4);
        }

        // compute on stage `cur`: 8 tokens x 4 expert-pairs over Kc=16
        const float* xs_c = &sbuf[cur * STAGE_FLOATS];
        const float* ws_c = &sbuf[cur * STAGE_FLOATS + KC * 132];
#pragma unroll
        for (int kk = 0; kk < KC; kk++) {
            float4 a0 = *(const float4*)(xs_c + kk * 132 + tx * 8);
            float4 a1 = *(const float4*)(xs_c + kk * 132 + tx * 8 + 4);
            float a[8] = {a0.x, a0.y, a0.z, a0.w, a1.x, a1.y, a1.z, a1.w};

            const ulonglong2* bp = (const ulonglong2*)(ws_c + kk * 68 + ty * 8);
            ulonglong2 bq0 = bp[0];
            ulonglong2 bq1 = bp[1];
            unsigned long long b2[4] = {bq0.x, bq0.y, bq1.x, bq1.y};

            unsigned long long as2[8];
#pragma unroll
            for (int i = 0; i < 8; i++) SPLAT_F32X2(as2[i], a[i]);

#pragma unroll
            for (int i = 0; i < 8; i++)
#pragma unroll
                for (int j = 0; j < 4; j++)
                    FMA_F32X2(acc2[i][j], as2[i], b2[j], acc2[i][j]);
        }

        // store prefetched chunk into stage `nxt` (disjoint from `cur`)
        if (c + 1 < NCHUNK) {
#pragma unroll
            for (int r = 0; r < 4; r++) {
                const int row = xl_r + r * 32;
                xs_at(nxt, xl_k + 0, row) = px[r].x;
                xs_at(nxt, xl_k + 1, row) = px[r].y;
                xs_at(nxt, xl_k + 2, row) = px[r].z;
                xs_at(nxt, xl_k + 3, row) = px[r].w;
            }
            ws_at(nxt, wl_k + 0, wl_e) = pw[0].x;
            ws_at(nxt, wl_k + 1, wl_e) = pw[0].y;
            ws_at(nxt, wl_k + 2, wl_e) = pw[0].z;
            ws_at(nxt, wl_k + 3, wl_e) = pw[0].w;
            ws_at(nxt, wl_k + 4, wl_e) = pw[1].x;
            ws_at(nxt, wl_k + 5, wl_e) = pw[1].y;
            ws_at(nxt, wl_k + 6, wl_e) = pw[1].z;
            ws_at(nxt, wl_k + 7, wl_e) = pw[1].w;
        }

        // one barrier per chunk: orders (a) this chunk's compute-reads before
        // next iteration's overwrite of `cur`, and (b) stores to `nxt` before
        // next iteration's compute-reads of it.
        __syncthreads();
    }

    // ---- epilogue: logits -> smem (staging buffers dead; reuse as lg) ----
#pragma unroll
    for (int i = 0; i < 8; i++)
#pragma unroll
        for (int j = 0; j < 4; j++) {
            unsigned int lo, hi;
            UNPACK_F32X2_(lo, hi, acc2[i][j]);
            lg[tx * 8 + i][ty * 8 + 2 * j + 0] = __uint_as_float(lo);
            lg[tx * 8 + i][ty * 8 + 2 * j + 1] = __uint_as_float(hi);
        }
    __syncthreads();

    // per-token branchless top-2 scan (thread tid owns local token tid).
    // Row read: bank = (65*tid + e) % 32 = (tid + e) % 32 -> conflict-free.
    {
        float m1 = -INFINITY, m2 = -INFINITY;
        int i1 = 0, i2 = 0;
#pragma unroll
        for (int e = 0; e < NEXP; e++) {
            float v = lg[tid][e];
            bool gt1 = v > m1;
            bool gt2 = v > m2;
            m2 = gt1 ? m1 : (gt2 ? v : m2);
            i2 = gt1 ? i1 : (gt2 ? e : i2);
            m1 = gt1 ? v : m1;
            i1 = gt1 ? e : i1;
        }
        // softmax over [m1, m2] (m1 >= m2, numerically stable)
        float t  = expf(m2 - m1);
        float w1 = 1.0f / (1.0f + t);
        float w2 = t * w1;

        const long tok = tokb + tid;
        __stcs(&wts_out[tok * 2 + 0], w1);
        __stcs(&wts_out[tok * 2 + 1], w2);
        __stcs(&idx_out[tok * 2 + 0], (float)i1);
        __stcs(&idx_out[tok * 2 + 1], (float)i2);
        s_i1[tid] = i1;
        s_i2[tid] = i2;
    }
    __syncthreads();

    // cooperative coalesced mask write: 128 tokens x 64 experts (streaming)
    float* mrow = mask_out + tokb * NEXP;
#pragma unroll 4
    for (int j = 0; j < NEXP; j++) {
        int flat = j * NTHREADS + tid;
        int t_ = flat >> 6;
        int e  = flat & 63;
        __stcs(&mrow[flat], (e == s_i1[t_] || e == s_i2[t_]) ? 1.0f : 0.0f);
    }
    (void)n_tokens;
}

extern "C" void kernel_launch(void* const* d_in, const int* in_sizes, int n_in,
                              void* d_out, int out_size) {
    const float* x  = (const float*)d_in[0];
    const float* gw = (const float*)d_in[1];

    const int n_tokens = in_sizes[0] / DIMK;  // 32768

    float* mask = (float*)d_out;
    float* wts  = mask + (long)n_tokens * NEXP;
    float* idxf = wts + (long)n_tokens * 2;

    const int nblocks = n_tokens / TOK_TILE;  // 256
    router_kernel<<<nblocks, NTHREADS>>>(x, gw, mask, wts, idxf, n_tokens);

    (void)n_in; (void)out_size;
}